// round 16
// baseline (speedup 1.0000x reference)
#include <cuda_runtime.h>
#include <cuda_bf16.h>

typedef unsigned long long ULL;

// Problem constants (fixed by setup_inputs)
#define IH 2160
#define IW 3840
#define HW (IH * IW)
#define KS 25
#define PADK 12
#define LH (IH + 22)
#define LW (IW + 22)
#define L3 (3 * LH * LW)

// Blur tiling: 32x32 outputs per block, 128 threads (4 warps x 8 cols, lane = row)
#define TILE 32
#define SROWS 56
#define SCOLS 56
#define SSTRIDE 57          // float2 stride for ch0/1 (odd -> conflict-free LDS.64)
#define S2STRIDE 29         // float2-pair stride for ch2 (conflict-free)
#define BLK_THREADS 128
#define RING 10             // ch0/1 rotating window slots
#define PRING 8             // ch2 pair-ring slots

#define GRID_X (IW / TILE)                    // 120
#define GRID_Y ((IH + TILE - 1) / TILE)       // 68

#define S01_BYTES (SROWS * SSTRIDE * 8)       // 25536
#define S2P_BYTES (SROWS * S2STRIDE * 8)      // 12992
#define SMEM_BYTES (S01_BYTES + S2P_BYTES)    // 38528 -> 6 blocks/SM

// Weights in constant memory:
//   c_w  : scalar floats  -> LDCU -> UR operand for scalar FFMA (rt=1)
//   c_w2 : duplicated (w,w) pairs -> UR64 operand for fma.rn.f32x2
__constant__ float c_w [KS * KS];
__constant__ ULL   c_w2[KS * KS];

// Laplacian partials + arrival counter (last lap block does the final reduce)
#define LAP_ROWS (3 * LH)            // 6546
#define LAP_VCHUNKS 958              // vector chunks: cc0 = 4 + 4c
__device__ float g_partials[LAP_ROWS];
__device__ unsigned int g_count = 0;

__device__ __forceinline__ int clampi(int v, int lo, int hi) {
    return min(max(v, lo), hi);
}

// ---------------------------------------------------------------------------
// Fused kernel: z=0 blocks do the 25x25 blur tile; z=1 blocks do one
// Laplacian row each. ONE shared buffer, manually unioned between the two
// branches (a block takes exactly one branch) -> 38.5 KB -> 6 blocks/SM.
// ---------------------------------------------------------------------------
__global__ void __launch_bounds__(BLK_THREADS, 6)
fused_kernel(const float* __restrict__ img,
             const float* __restrict__ noise,
             float* __restrict__ out,
             float* __restrict__ out_scalar)
{
    __shared__ __align__(16) char smem_raw[SMEM_BYTES];
    const int tid = threadIdx.x;

    if (blockIdx.z == 1) {
        // ================= Laplacian row =================
        float*        sbuf      = reinterpret_cast<float*>(smem_raw);
        double*       sd        = reinterpret_cast<double*>(smem_raw + 512);
        unsigned int* s_arrival = reinterpret_cast<unsigned int*>(smem_raw + 512 + 1024);

        const int row = blockIdx.y * GRID_X + blockIdx.x;
        if (row >= LAP_ROWS) return;
        const int ch  = row / LH;
        const int oy  = row - ch * LH;
        const float* p = img + ch * HW;

        const int ru = clampi(oy - 12, 0, IH - 1);
        const int rc = clampi(oy - 11, 0, IH - 1);
        const int rd = clampi(oy - 10, 0, IH - 1);
        const float* __restrict__ pu = p + ru * IW;
        const float* __restrict__ pc = p + rc * IW;
        const float* __restrict__ pd = p + rd * IW;

        float acc = 0.0f;

        for (int c = tid; c < LAP_VCHUNKS; c += BLK_THREADS) {
            int cc0 = 4 + 4 * c;
            float4 u = *reinterpret_cast<const float4*>(pu + cc0);
            float4 m = *reinterpret_cast<const float4*>(pc + cc0);
            float4 d = *reinterpret_cast<const float4*>(pd + cc0);
            float l = pc[cc0 - 1];
            float r = pc[cc0 + 4];
            float v0 = 4.0f * m.x - u.x - d.x - l   - m.y;
            float v1 = 4.0f * m.y - u.y - d.y - m.x - m.z;
            float v2 = 4.0f * m.z - u.z - d.z - m.y - m.w;
            float v3 = 4.0f * m.w - u.w - d.w - m.z - r;
            acc = fmaf(v0, v0, acc);
            acc = fmaf(v1, v1, acc);
            acc = fmaf(v2, v2, acc);
            acc = fmaf(v3, v3, acc);
        }

        if (tid < 30) {
            int ox = (tid < 15) ? tid : (3832 + tid);
            int cl = clampi(ox - 12, 0, IW - 1);
            int cc = clampi(ox - 11, 0, IW - 1);
            int cr = clampi(ox - 10, 0, IW - 1);
            float v = 4.0f * pc[cc] - pu[cc] - pd[cc] - pc[cl] - pc[cr];
            acc = fmaf(v, v, acc);
        }

        sbuf[tid] = acc;
        __syncthreads();
#pragma unroll
        for (int s = BLK_THREADS / 2; s > 0; s >>= 1) {
            if (tid < s) sbuf[tid] += sbuf[tid + s];
            __syncthreads();
        }

        if (tid == 0) {
            g_partials[row] = sbuf[0];
            __threadfence();                          // publish partial
            *s_arrival = atomicAdd(&g_count, 1u);     // arrival ticket
        }
        __syncthreads();

        if (*s_arrival == LAP_ROWS - 1) {
            // last lap block: deterministic fixed-order final reduction
            double s0 = 0.0, s1 = 0.0;
            for (int i = tid; i < LAP_ROWS; i += 2 * BLK_THREADS) {
                s0 += (double)g_partials[i];
                if (i + BLK_THREADS < LAP_ROWS)
                    s1 += (double)g_partials[i + BLK_THREADS];
            }
            sd[tid] = s0 + s1;
            __syncthreads();
#pragma unroll
            for (int k = BLK_THREADS / 2; k > 0; k >>= 1) {
                if (tid < k) sd[tid] += sd[tid + k];
                __syncthreads();
            }
            if (tid == 0) {
                out_scalar[0] = (float)(sd[0] / (double)L3);
                g_count = 0;                          // reset for next replay
            }
        }
        return;
    }

    // ================= Blur tile =================
    float2* s01 = reinterpret_cast<float2*>(smem_raw);               // [56 x 57]
    float2* s2p = reinterpret_cast<float2*>(smem_raw + S01_BYTES);   // [56 x 29]

    const int tx0 = blockIdx.x * TILE;
    const int ty0 = blockIdx.y * TILE;

    const bool interior = (blockIdx.x >= 1) & (blockIdx.x <= GRID_X - 2) &
                          (blockIdx.y >= 1) & (blockIdx.y <= GRID_Y - 2);

    if (interior) {
        // fast path: no clamping, float4 loads (16B-aligned by construction)
        const float* b0 = img + (ty0 - PADK) * IW + (tx0 - PADK);
        float* s2f = reinterpret_cast<float*>(s2p);   // float stride 58
        for (int q = tid; q < SROWS * 14; q += BLK_THREADS) {
            int r  = q / 14;
            int c4 = (q - r * 14) * 4;
            const float* p = b0 + r * IW + c4;
            float4 v0 = *reinterpret_cast<const float4*>(p);
            float4 v1 = *reinterpret_cast<const float4*>(p + HW);
            float4 v2 = *reinterpret_cast<const float4*>(p + 2 * HW);
            float2* d01 = s01 + r * SSTRIDE + c4;
            d01[0] = make_float2(v0.x, v1.x);
            d01[1] = make_float2(v0.y, v1.y);
            d01[2] = make_float2(v0.z, v1.z);
            d01[3] = make_float2(v0.w, v1.w);
            float* d2 = s2f + r * (2 * S2STRIDE) + c4;   // 8B-aligned
            *reinterpret_cast<float2*>(d2)     = make_float2(v2.x, v2.y);
            *reinterpret_cast<float2*>(d2 + 2) = make_float2(v2.z, v2.w);
        }
    } else {
        // clamped scalar path (edge blocks only)
        int r = tid / SCOLS;
        int c = tid - r * SCOLS;
        float* s2f = reinterpret_cast<float*>(s2p);
        for (int i = tid; i < SROWS * SCOLS; i += BLK_THREADS) {
            int gy = clampi(ty0 - PADK + r, 0, IH - 1);
            int gx = clampi(tx0 - PADK + c, 0, IW - 1);
            int gi = gy * IW + gx;
            s01[r * SSTRIDE + c] = make_float2(img[gi], img[HW + gi]);
            s2f[r * (2 * S2STRIDE) + c] = img[2 * HW + gi];
            r += 2; c += 16;                          // 128 = 2*56 + 16
            if (c >= SCOLS) { c -= SCOLS; r += 1; }
        }
    }
    __syncthreads();

    const int lane = tid & 31;      // output row within tile
    const int wid  = tid >> 5;      // x-group (0..3)
    const int xb   = wid * 8;       // column base within tile (even)

    ULL   acc01[8];
    float acc2 [8];
#pragma unroll
    for (int j = 0; j < 8; j++) { acc01[j] = 0ull; acc2[j] = 0.0f; }

#pragma unroll 1
    for (int ky = 0; ky < KS; ++ky) {
        const ULL*    rowp = reinterpret_cast<const ULL*>(s01 + (lane + ky) * SSTRIDE + xb);
        const float2* p2   = s2p + (lane + ky) * S2STRIDE + (xb >> 1);
        const int wbase = ky * KS;

        ULL    a [RING];           // ch0/1 columns xb+0 .. xb+9
        float2 cp[PRING];          // ch2 even pairs 0..5 (cols 0..11)
#pragma unroll
        for (int i = 0; i < RING; i++) a[i] = rowp[i];
#pragma unroll
        for (int i = 0; i < 6; i++) cp[i] = p2[i];

#pragma unroll
        for (int kx = 0; kx < KS; ++kx) {
            const ULL   ww = c_w2[wbase + kx];  // uniform -> UR64
            const float wv = c_w [wbase + kx];  // uniform -> UR
#pragma unroll
            for (int j = 0; j < 8; j++) {
                const int s = (kx + j) % RING;          // compile-time
                asm("fma.rn.f32x2 %0, %1, %2, %0;"
                    : "+l"(acc01[j]) : "l"(a[s]), "l"(ww));
                const int p  = ((kx + j) >> 1) & (PRING - 1);
                const float d2 = ((kx + j) & 1) ? cp[p].y : cp[p].x;
                acc2[j] = fmaf(d2, wv, acc2[j]);
            }
            if (kx < KS - 3)                            // ch0/1 cols 10..31
                a[kx % RING] = rowp[RING + kx];
            if ((kx & 1) == 0 && kx <= 18)              // ch2 pairs 6..15
                cp[(kx / 2 + 6) & (PRING - 1)] = p2[kx / 2 + 6];
        }
    }

    const int y = ty0 + lane;
    if (y < IH) {                               // last block row is half-tall
        const int x = tx0 + xb;
        const int base = y * IW + x;
        float4 n0 = *reinterpret_cast<const float4*>(noise + base);
        float4 n1 = *reinterpret_cast<const float4*>(noise + base + 4);

        float v0[8], v1[8];
#pragma unroll
        for (int j = 0; j < 8; j++) {
            float2 f = *reinterpret_cast<float2*>(&acc01[j]);
            v0[j] = f.x; v1[j] = f.y;
        }
        *reinterpret_cast<float4*>(out + 0 * HW + base) =
            make_float4(v0[0] + n0.x, v0[1] + n0.y, v0[2] + n0.z, v0[3] + n0.w);
        *reinterpret_cast<float4*>(out + 0 * HW + base + 4) =
            make_float4(v0[4] + n1.x, v0[5] + n1.y, v0[6] + n1.z, v0[7] + n1.w);
        *reinterpret_cast<float4*>(out + 1 * HW + base) =
            make_float4(v1[0] + n0.x, v1[1] + n0.y, v1[2] + n0.z, v1[3] + n0.w);
        *reinterpret_cast<float4*>(out + 1 * HW + base + 4) =
            make_float4(v1[4] + n1.x, v1[5] + n1.y, v1[6] + n1.z, v1[7] + n1.w);
        *reinterpret_cast<float4*>(out + 2 * HW + base) =
            make_float4(acc2[0] + n0.x, acc2[1] + n0.y, acc2[2] + n0.z, acc2[3] + n0.w);
        *reinterpret_cast<float4*>(out + 2 * HW + base + 4) =
            make_float4(acc2[4] + n1.x, acc2[5] + n1.y, acc2[6] + n1.z, acc2[7] + n1.w);
    }
}

extern "C" void kernel_launch(void* const* d_in, const int* in_sizes, int n_in,
                              void* d_out, int out_size)
{
    const float* img   = (const float*)d_in[0];  // (1,3,2160,3840)
    const float* noise = (const float*)d_in[1];  // (1,1,2160,3840)
    const float* g     = (const float*)d_in[2];  // (25,25)
    float* out = (float*)d_out;                  // [3*H*W conv output, 1 scalar]

    // Scalar weights -> c_w (dense copy, proven LDCU->UR path).
    cudaMemcpyToSymbolAsync(c_w, g, KS * KS * sizeof(float), 0,
                            cudaMemcpyDeviceToDevice, 0);

    // Duplicated (w,w) pairs -> c_w2 via two strided D2D 2D-memcpys.
    void* w2_ptr = nullptr;
    cudaGetSymbolAddress(&w2_ptr, c_w2);
    cudaMemcpy2DAsync(w2_ptr, 8, g, 4, 4, KS * KS,
                      cudaMemcpyDeviceToDevice, 0);                 // low halves
    cudaMemcpy2DAsync((char*)w2_ptr + 4, 8, g, 4, 4, KS * KS,
                      cudaMemcpyDeviceToDevice, 0);                 // high halves

    // z=0: 120x68 blur tiles.  z=1: Laplacian rows (flat id); last lap block
    // performs the final reduction and writes the scalar.
    dim3 gridF(GRID_X, GRID_Y, 2);
    fused_kernel<<<gridF, BLK_THREADS>>>(img, noise, out, out + (out_size - 1));
}

// round 17
// speedup vs baseline: 1.0728x; 1.0728x over previous
#include <cuda_runtime.h>
#include <cuda_bf16.h>

typedef unsigned long long ULL;

// Problem constants (fixed by setup_inputs)
#define IH 2160
#define IW 3840
#define HW (IH * IW)
#define KS 25
#define PADK 12
#define LH (IH + 22)
#define LW (IW + 22)
#define L3 (3 * LH * LW)

// Blur tiling: 32x32 outputs per block, 128 threads (4 warps x 8 cols, lane = row)
#define TILE 32
#define SROWS 56
#define SCOLS 56
#define SSTRIDE 57          // float2 stride for ch0/1 (odd -> conflict-free LDS.64)
#define S2STRIDE 29         // float2-pair stride for ch2 (conflict-free)
#define BLK_THREADS 128
#define RING 10             // ch0/1 rotating window slots
#define PRING 8             // ch2 pair-ring slots

#define GRID_X (IW / TILE)                    // 120
#define GRID_Y ((IH + TILE - 1) / TILE)       // 68

// Weights in constant memory:
//   c_w  : scalar floats  -> LDCU -> UR operand for scalar FFMA (rt=1)
//   c_w2 : duplicated (w,w) pairs -> UR64 operand for fma.rn.f32x2
__constant__ float c_w [KS * KS];
__constant__ ULL   c_w2[KS * KS];

// Laplacian
#define LAP_ROWS (3 * LH)            // 6546
#define LAP_VCHUNKS 958              // vector chunks: cc0 = 4 + 4c
__device__ float g_partials[LAP_ROWS];

__device__ __forceinline__ int clampi(int v, int lo, int hi) {
    return min(max(v, lo), hi);
}

// ---------------------------------------------------------------------------
// Fused kernel: z=0 blocks do the 25x25 blur tile; z=1 blocks do one
// Laplacian row each (dispatched after all blur blocks -> fill blur tail).
// ---------------------------------------------------------------------------
__global__ void __launch_bounds__(BLK_THREADS)
fused_kernel(const float* __restrict__ img,
             const float* __restrict__ noise,
             float* __restrict__ out)
{
    const int tid = threadIdx.x;

    if (blockIdx.z == 1) {
        // ================= Laplacian row =================
        const int row = blockIdx.y * GRID_X + blockIdx.x;
        if (row >= LAP_ROWS) return;
        const int ch  = row / LH;
        const int oy  = row - ch * LH;
        const float* p = img + ch * HW;

        const int ru = clampi(oy - 12, 0, IH - 1);
        const int rc = clampi(oy - 11, 0, IH - 1);
        const int rd = clampi(oy - 10, 0, IH - 1);
        const float* __restrict__ pu = p + ru * IW;
        const float* __restrict__ pc = p + rc * IW;
        const float* __restrict__ pd = p + rd * IW;

        float acc = 0.0f;

        for (int c = tid; c < LAP_VCHUNKS; c += BLK_THREADS) {
            int cc0 = 4 + 4 * c;
            float4 u = *reinterpret_cast<const float4*>(pu + cc0);
            float4 m = *reinterpret_cast<const float4*>(pc + cc0);
            float4 d = *reinterpret_cast<const float4*>(pd + cc0);
            float l = pc[cc0 - 1];
            float r = pc[cc0 + 4];
            float v0 = 4.0f * m.x - u.x - d.x - l   - m.y;
            float v1 = 4.0f * m.y - u.y - d.y - m.x - m.z;
            float v2 = 4.0f * m.z - u.z - d.z - m.y - m.w;
            float v3 = 4.0f * m.w - u.w - d.w - m.z - r;
            acc = fmaf(v0, v0, acc);
            acc = fmaf(v1, v1, acc);
            acc = fmaf(v2, v2, acc);
            acc = fmaf(v3, v3, acc);
        }

        if (tid < 30) {
            int ox = (tid < 15) ? tid : (3832 + tid);
            int cl = clampi(ox - 12, 0, IW - 1);
            int cc = clampi(ox - 11, 0, IW - 1);
            int cr = clampi(ox - 10, 0, IW - 1);
            float v = 4.0f * pc[cc] - pu[cc] - pd[cc] - pc[cl] - pc[cr];
            acc = fmaf(v, v, acc);
        }

        __shared__ float sbuf[BLK_THREADS];
        sbuf[tid] = acc;
        __syncthreads();
#pragma unroll
        for (int s = BLK_THREADS / 2; s > 0; s >>= 1) {
            if (tid < s) sbuf[tid] += sbuf[tid + s];
            __syncthreads();
        }
        if (tid == 0) g_partials[row] = sbuf[0];
        return;
    }

    // ================= Blur tile =================
    __shared__ float2 s01[SROWS * SSTRIDE];    // channels 0,1 packed
    __shared__ float2 s2p[SROWS * S2STRIDE];   // channel 2, even-column pairs

    const int tx0 = blockIdx.x * TILE;
    const int ty0 = blockIdx.y * TILE;

    const bool interior = (blockIdx.x >= 1) & (blockIdx.x <= GRID_X - 2) &
                          (blockIdx.y >= 1) & (blockIdx.y <= GRID_Y - 2);

    if (interior) {
        // fast path: no clamping, float4 loads (16B-aligned by construction)
        const float* b0 = img + (ty0 - PADK) * IW + (tx0 - PADK);
        float* s2f = reinterpret_cast<float*>(s2p);   // float stride 58
        for (int q = tid; q < SROWS * 14; q += BLK_THREADS) {
            int r  = q / 14;
            int c4 = (q - r * 14) * 4;
            const float* p = b0 + r * IW + c4;
            float4 v0 = *reinterpret_cast<const float4*>(p);
            float4 v1 = *reinterpret_cast<const float4*>(p + HW);
            float4 v2 = *reinterpret_cast<const float4*>(p + 2 * HW);
            float2* d01 = s01 + r * SSTRIDE + c4;
            d01[0] = make_float2(v0.x, v1.x);
            d01[1] = make_float2(v0.y, v1.y);
            d01[2] = make_float2(v0.z, v1.z);
            d01[3] = make_float2(v0.w, v1.w);
            float* d2 = s2f + r * (2 * S2STRIDE) + c4;   // 8B-aligned
            *reinterpret_cast<float2*>(d2)     = make_float2(v2.x, v2.y);
            *reinterpret_cast<float2*>(d2 + 2) = make_float2(v2.z, v2.w);
        }
    } else {
        // clamped scalar path (edge blocks only)
        int r = tid / SCOLS;
        int c = tid - r * SCOLS;
        float* s2f = reinterpret_cast<float*>(s2p);
        for (int i = tid; i < SROWS * SCOLS; i += BLK_THREADS) {
            int gy = clampi(ty0 - PADK + r, 0, IH - 1);
            int gx = clampi(tx0 - PADK + c, 0, IW - 1);
            int gi = gy * IW + gx;
            s01[r * SSTRIDE + c] = make_float2(img[gi], img[HW + gi]);
            s2f[r * (2 * S2STRIDE) + c] = img[2 * HW + gi];
            r += 2; c += 16;                          // 128 = 2*56 + 16
            if (c >= SCOLS) { c -= SCOLS; r += 1; }
        }
    }
    __syncthreads();

    const int lane = tid & 31;      // output row within tile
    const int wid  = tid >> 5;      // x-group (0..3)
    const int xb   = wid * 8;       // column base within tile (even)

    ULL   acc01[8];
    float acc2 [8];
#pragma unroll
    for (int j = 0; j < 8; j++) { acc01[j] = 0ull; acc2[j] = 0.0f; }

#pragma unroll 1
    for (int ky = 0; ky < KS; ++ky) {
        const ULL*    rowp = reinterpret_cast<const ULL*>(s01 + (lane + ky) * SSTRIDE + xb);
        const float2* p2   = s2p + (lane + ky) * S2STRIDE + (xb >> 1);
        const int wbase = ky * KS;

        ULL    a [RING];           // ch0/1 columns xb+0 .. xb+9
        float2 cp[PRING];          // ch2 even pairs 0..5 (cols 0..11)
#pragma unroll
        for (int i = 0; i < RING; i++) a[i] = rowp[i];
#pragma unroll
        for (int i = 0; i < 6; i++) cp[i] = p2[i];

#pragma unroll
        for (int kx = 0; kx < KS; ++kx) {
            const ULL   ww = c_w2[wbase + kx];  // uniform -> UR64
            const float wv = c_w [wbase + kx];  // uniform -> UR
#pragma unroll
            for (int j = 0; j < 8; j++) {
                const int s = (kx + j) % RING;          // compile-time
                asm("fma.rn.f32x2 %0, %1, %2, %0;"
                    : "+l"(acc01[j]) : "l"(a[s]), "l"(ww));
                const int p  = ((kx + j) >> 1) & (PRING - 1);
                const float d2 = ((kx + j) & 1) ? cp[p].y : cp[p].x;
                acc2[j] = fmaf(d2, wv, acc2[j]);
            }
            if (kx < KS - 3)                            // ch0/1 cols 10..31
                a[kx % RING] = rowp[RING + kx];
            if ((kx & 1) == 0 && kx <= 18)              // ch2 pairs 6..15
                cp[(kx / 2 + 6) & (PRING - 1)] = p2[kx / 2 + 6];
        }
    }

    const int y = ty0 + lane;
    if (y < IH) {                               // last block row is half-tall
        const int x = tx0 + xb;
        const int base = y * IW + x;
        float4 n0 = *reinterpret_cast<const float4*>(noise + base);
        float4 n1 = *reinterpret_cast<const float4*>(noise + base + 4);

        float v0[8], v1[8];
#pragma unroll
        for (int j = 0; j < 8; j++) {
            float2 f = *reinterpret_cast<float2*>(&acc01[j]);
            v0[j] = f.x; v1[j] = f.y;
        }
        *reinterpret_cast<float4*>(out + 0 * HW + base) =
            make_float4(v0[0] + n0.x, v0[1] + n0.y, v0[2] + n0.z, v0[3] + n0.w);
        *reinterpret_cast<float4*>(out + 0 * HW + base + 4) =
            make_float4(v0[4] + n1.x, v0[5] + n1.y, v0[6] + n1.z, v0[7] + n1.w);
        *reinterpret_cast<float4*>(out + 1 * HW + base) =
            make_float4(v1[0] + n0.x, v1[1] + n0.y, v1[2] + n0.z, v1[3] + n0.w);
        *reinterpret_cast<float4*>(out + 1 * HW + base + 4) =
            make_float4(v1[4] + n1.x, v1[5] + n1.y, v1[6] + n1.z, v1[7] + n1.w);
        *reinterpret_cast<float4*>(out + 2 * HW + base) =
            make_float4(acc2[0] + n0.x, acc2[1] + n0.y, acc2[2] + n0.z, acc2[3] + n0.w);
        *reinterpret_cast<float4*>(out + 2 * HW + base + 4) =
            make_float4(acc2[4] + n1.x, acc2[5] + n1.y, acc2[6] + n1.z, acc2[7] + n1.w);
    }
}

// ---------------------------------------------------------------------------
// Final deterministic reduction in double -> mean scalar.
// ---------------------------------------------------------------------------
__global__ void __launch_bounds__(256)
reduce_kernel(float* __restrict__ out_scalar)
{
    __shared__ double sd[256];
    double s0 = 0.0, s1 = 0.0, s2 = 0.0, s3 = 0.0;
    for (int i = threadIdx.x; i < LAP_ROWS; i += 1024) {
        if (i       < LAP_ROWS) s0 += (double)g_partials[i];
        if (i + 256 < LAP_ROWS) s1 += (double)g_partials[i + 256];
        if (i + 512 < LAP_ROWS) s2 += (double)g_partials[i + 512];
        if (i + 768 < LAP_ROWS) s3 += (double)g_partials[i + 768];
    }
    sd[threadIdx.x] = (s0 + s1) + (s2 + s3);
    __syncthreads();
#pragma unroll
    for (int k = 128; k > 0; k >>= 1) {
        if (threadIdx.x < k) sd[threadIdx.x] += sd[threadIdx.x + k];
        __syncthreads();
    }
    if (threadIdx.x == 0)
        out_scalar[0] = (float)(sd[0] / (double)L3);
}

extern "C" void kernel_launch(void* const* d_in, const int* in_sizes, int n_in,
                              void* d_out, int out_size)
{
    const float* img   = (const float*)d_in[0];  // (1,3,2160,3840)
    const float* noise = (const float*)d_in[1];  // (1,1,2160,3840)
    const float* g     = (const float*)d_in[2];  // (25,25)
    float* out = (float*)d_out;                  // [3*H*W conv output, 1 scalar]

    // Scalar weights -> c_w (dense copy, proven LDCU->UR path).
    cudaMemcpyToSymbolAsync(c_w, g, KS * KS * sizeof(float), 0,
                            cudaMemcpyDeviceToDevice, 0);

    // Duplicated (w,w) pairs -> c_w2 via two strided D2D 2D-memcpys
    // (no staging kernel).
    void* w2_ptr = nullptr;
    cudaGetSymbolAddress(&w2_ptr, c_w2);
    cudaMemcpy2DAsync(w2_ptr, 8, g, 4, 4, KS * KS,
                      cudaMemcpyDeviceToDevice, 0);                 // low halves
    cudaMemcpy2DAsync((char*)w2_ptr + 4, 8, g, 4, 4, KS * KS,
                      cudaMemcpyDeviceToDevice, 0);                 // high halves

    // z=0: 120x68 blur tiles.  z=1: Laplacian rows (flat id).
    dim3 gridF(GRID_X, GRID_Y, 2);
    fused_kernel<<<gridF, BLK_THREADS>>>(img, noise, out);

    reduce_kernel<<<1, 256>>>(out + (out_size - 1));
}